// round 1
// baseline (speedup 1.0000x reference)
#include <cuda_runtime.h>

#define Bn 8
#define Tt 64
#define Nn 128
#define Dd 128
#define TWw 62

// scratch (allocation-free rule: __device__ globals)
__device__ float g_wf[Bn * Tt * Nn * Dd];   // gated + L2-normalized feat
__device__ float g_P[Bn * Tt * Dd];         // per-(b,t) node-sum of wf

// ---------------------------------------------------------------------------
// Kernel 1: wf = (feat * sigmoid(w)) / max(||.||2, 1e-12), one warp per row
// ---------------------------------------------------------------------------
__global__ __launch_bounds__(256) void wf_kernel(const float* __restrict__ feat,
                                                 const float* __restrict__ w) {
    __shared__ float sigw[Dd];
    int tid = threadIdx.x;
    if (tid < Dd) sigw[tid] = 1.0f / (1.0f + expf(-w[tid]));
    __syncthreads();

    int warp = tid >> 5, lane = tid & 31;
    size_t row = (size_t)blockIdx.x * 8 + warp;          // 65536 rows total
    const float4* src = (const float4*)(feat + row * Dd);
    float4 v = src[lane];
    float4 sw = ((const float4*)sigw)[lane];
    v.x *= sw.x; v.y *= sw.y; v.z *= sw.z; v.w *= sw.w;
    float sq = v.x * v.x + v.y * v.y + v.z * v.z + v.w * v.w;
#pragma unroll
    for (int off = 16; off; off >>= 1) sq += __shfl_xor_sync(0xffffffffu, sq, off);
    float scale = 1.0f / fmaxf(sqrtf(sq), 1e-12f);
    v.x *= scale; v.y *= scale; v.z *= scale; v.w *= scale;
    ((float4*)(g_wf + row * Dd))[lane] = v;
}

// ---------------------------------------------------------------------------
// Kernel 2: P[b][t][d] = sum_n wf[b,t,n,d]
// ---------------------------------------------------------------------------
__global__ __launch_bounds__(128) void psum_kernel() {
    int bt = blockIdx.x;
    int d = threadIdx.x;
    const float* base = g_wf + (size_t)bt * Nn * Dd + d;
    float s = 0.0f;
#pragma unroll 4
    for (int n = 0; n < Nn; n++) s += base[n * Dd];
    g_P[bt * Dd + d] = s;
}

// ---------------------------------------------------------------------------
// Kernel 3: one block per (b, tw) window. 256 threads, 8x8 register tiles.
//   dis_j = f(S . wf_j)             (384 dots)
//   M     = wf^T diag(dis) feat     (128x128, K=384)
//   agg   = diag(dis_last) wf_last @ M
//   t1    = relu(agg @ W1 + b1); t2 = t1 @ W2 + b2
//   out   = LN(feat_last + t2) * gamma + beta
// ---------------------------------------------------------------------------
#define SMEM_FLOATS 41472
#define SMEM_BYTES  (SMEM_FLOATS * 4)

__global__ __launch_bounds__(256, 1)
void fused_kernel(const float* __restrict__ feat,
                  const float* __restrict__ W1, const float* __restrict__ b1,
                  const float* __restrict__ W2, const float* __restrict__ b2,
                  const float* __restrict__ gamma, const float* __restrict__ beta,
                  float* __restrict__ out) {
    extern __shared__ float sm[];
    float* tileA = sm;              // 32 x 128  (4096)
    float* tileB = sm + 4096;       // 32 x 128  (4096)
    float* Ms    = sm + 8192;       // 128 x 128 (16384): M, then W1, then W2
    float* Xs    = sm + 24576;      // 128 x 128 (16384): wf_last, agg, t1
    float* dis   = sm + 40960;      // 384
    float* Sv    = sm + 41344;      // 128

    const int tid = threadIdx.x;
    const int bw = blockIdx.x;                  // 0..495
    const int b = bw / TWw, tw = bw % TWw;
    const float* win  = feat + (size_t)(b * Tt + tw) * Nn * Dd;   // 384x128 contiguous
    const float* wwin = g_wf + (size_t)(b * Tt + tw) * Nn * Dd;

    // ---- Stage A: window sum S from precomputed per-timestep sums
    if (tid < Dd) {
        int base = (b * Tt + tw) * Dd + tid;
        Sv[tid] = g_P[base] + g_P[base + Dd] + g_P[base + 2 * Dd];
    }
    __syncthreads();

    // ---- Stage B: dis_j = deg>0 ? rsqrt(max(deg,1e-38)) : 0, deg = S.wf_j
    {
        int warp = tid >> 5, lane = tid & 31;
        float4 s4 = ((const float4*)Sv)[lane];
        for (int j = warp; j < 3 * Nn; j += 8) {
            float4 v = ((const float4*)(wwin + j * Dd))[lane];
            float p = v.x * s4.x + v.y * s4.y + v.z * s4.z + v.w * s4.w;
#pragma unroll
            for (int off = 16; off; off >>= 1) p += __shfl_xor_sync(0xffffffffu, p, off);
            if (lane == 0) dis[j] = (p > 0.0f) ? rsqrtf(fmaxf(p, 1e-38f)) : 0.0f;
        }
    }
    __syncthreads();

    const int ty = tid >> 4, tx = tid & 15;
    const int row0 = ty * 8, col0 = tx * 8;
    float acc[8][8];

    // ---- Stage C: M[d1][d2] = sum_j dis_j * wf[j][d1] * feat[j][d2]  (K=384)
#pragma unroll
    for (int i = 0; i < 8; i++)
#pragma unroll
        for (int j = 0; j < 8; j++) acc[i][j] = 0.0f;

    for (int kc = 0; kc < 12; kc++) {
        for (int i = tid; i < 1024; i += 256) {
            int kl = i >> 5;                            // row within 32-chunk
            float dj = dis[kc * 32 + kl];
            float4 a = ((const float4*)(wwin + kc * 4096))[i];
            a.x *= dj; a.y *= dj; a.z *= dj; a.w *= dj;
            ((float4*)tileA)[i] = a;
            ((float4*)tileB)[i] = ((const float4*)(win + kc * 4096))[i];
        }
        __syncthreads();
#pragma unroll 2
        for (int k = 0; k < 32; k++) {
            float4 a0 = *(const float4*)&tileA[k * 128 + row0];
            float4 a1 = *(const float4*)&tileA[k * 128 + row0 + 4];
            float4 c0 = *(const float4*)&tileB[k * 128 + col0];
            float4 c1 = *(const float4*)&tileB[k * 128 + col0 + 4];
            float ar[8] = {a0.x, a0.y, a0.z, a0.w, a1.x, a1.y, a1.z, a1.w};
            float br[8] = {c0.x, c0.y, c0.z, c0.w, c1.x, c1.y, c1.z, c1.w};
#pragma unroll
            for (int i = 0; i < 8; i++)
#pragma unroll
                for (int j = 0; j < 8; j++) acc[i][j] += ar[i] * br[j];
        }
        __syncthreads();
    }
    // write M, load wf_last into Xs
#pragma unroll
    for (int i = 0; i < 8; i++)
#pragma unroll
        for (int j = 0; j < 8; j++) Ms[(row0 + i) * 128 + col0 + j] = acc[i][j];
    for (int i = tid; i < 4096; i += 256)
        ((float4*)Xs)[i] = ((const float4*)(wwin + 2 * Nn * Dd))[i];
    __syncthreads();

    // ---- Stage D: agg = diag(dis[256..]) * (wf_last @ M)
#pragma unroll
    for (int i = 0; i < 8; i++)
#pragma unroll
        for (int j = 0; j < 8; j++) acc[i][j] = 0.0f;
#pragma unroll 2
    for (int k = 0; k < 128; k++) {
        float4 c0 = *(const float4*)&Ms[k * 128 + col0];
        float4 c1 = *(const float4*)&Ms[k * 128 + col0 + 4];
        float br[8] = {c0.x, c0.y, c0.z, c0.w, c1.x, c1.y, c1.z, c1.w};
        float ar[8];
#pragma unroll
        for (int i = 0; i < 8; i++) ar[i] = Xs[(row0 + i) * 128 + k];
#pragma unroll
        for (int i = 0; i < 8; i++)
#pragma unroll
            for (int j = 0; j < 8; j++) acc[i][j] += ar[i] * br[j];
    }
    {
        float di[8];
#pragma unroll
        for (int i = 0; i < 8; i++) di[i] = dis[2 * Nn + row0 + i];
#pragma unroll
        for (int i = 0; i < 8; i++)
#pragma unroll
            for (int j = 0; j < 8; j++) acc[i][j] *= di[i];
    }
    __syncthreads();
#pragma unroll
    for (int i = 0; i < 8; i++)
#pragma unroll
        for (int j = 0; j < 8; j++) Xs[(row0 + i) * 128 + col0 + j] = acc[i][j];
    for (int i = tid; i < 4096; i += 256)
        ((float4*)Ms)[i] = ((const float4*)W1)[i];
    __syncthreads();

    // ---- Stage E: t1 = relu(agg @ W1 + b1)
#pragma unroll
    for (int i = 0; i < 8; i++)
#pragma unroll
        for (int j = 0; j < 8; j++) acc[i][j] = 0.0f;
#pragma unroll 2
    for (int k = 0; k < 128; k++) {
        float4 c0 = *(const float4*)&Ms[k * 128 + col0];
        float4 c1 = *(const float4*)&Ms[k * 128 + col0 + 4];
        float br[8] = {c0.x, c0.y, c0.z, c0.w, c1.x, c1.y, c1.z, c1.w};
        float ar[8];
#pragma unroll
        for (int i = 0; i < 8; i++) ar[i] = Xs[(row0 + i) * 128 + k];
#pragma unroll
        for (int i = 0; i < 8; i++)
#pragma unroll
            for (int j = 0; j < 8; j++) acc[i][j] += ar[i] * br[j];
    }
    {
        float4 v0 = ((const float4*)b1)[tx * 2];
        float4 v1 = ((const float4*)b1)[tx * 2 + 1];
        float bj[8] = {v0.x, v0.y, v0.z, v0.w, v1.x, v1.y, v1.z, v1.w};
#pragma unroll
        for (int i = 0; i < 8; i++)
#pragma unroll
            for (int j = 0; j < 8; j++) acc[i][j] = fmaxf(acc[i][j] + bj[j], 0.0f);
    }
    __syncthreads();
#pragma unroll
    for (int i = 0; i < 8; i++)
#pragma unroll
        for (int j = 0; j < 8; j++) Xs[(row0 + i) * 128 + col0 + j] = acc[i][j];
    for (int i = tid; i < 4096; i += 256)
        ((float4*)Ms)[i] = ((const float4*)W2)[i];
    __syncthreads();

    // ---- Stage F: t2 = t1 @ W2 + b2; s = feat_last + t2; LayerNorm
#pragma unroll
    for (int i = 0; i < 8; i++)
#pragma unroll
        for (int j = 0; j < 8; j++) acc[i][j] = 0.0f;
#pragma unroll 2
    for (int k = 0; k < 128; k++) {
        float4 c0 = *(const float4*)&Ms[k * 128 + col0];
        float4 c1 = *(const float4*)&Ms[k * 128 + col0 + 4];
        float br[8] = {c0.x, c0.y, c0.z, c0.w, c1.x, c1.y, c1.z, c1.w};
        float ar[8];
#pragma unroll
        for (int i = 0; i < 8; i++) ar[i] = Xs[(row0 + i) * 128 + k];
#pragma unroll
        for (int i = 0; i < 8; i++)
#pragma unroll
            for (int j = 0; j < 8; j++) acc[i][j] += ar[i] * br[j];
    }

    {
        float4 v0 = ((const float4*)b2)[tx * 2];
        float4 v1 = ((const float4*)b2)[tx * 2 + 1];
        float bj[8] = {v0.x, v0.y, v0.z, v0.w, v1.x, v1.y, v1.z, v1.w};
        float4 g0 = ((const float4*)gamma)[tx * 2];
        float4 g1 = ((const float4*)gamma)[tx * 2 + 1];
        float gj[8] = {g0.x, g0.y, g0.z, g0.w, g1.x, g1.y, g1.z, g1.w};
        float4 e0 = ((const float4*)beta)[tx * 2];
        float4 e1 = ((const float4*)beta)[tx * 2 + 1];
        float ej[8] = {e0.x, e0.y, e0.z, e0.w, e1.x, e1.y, e1.z, e1.w};

        const float* fl = win + 2 * Nn * Dd;       // feat[b, tw+2]
        float* outp = out + (size_t)(b * TWw + tw) * Nn * Dd;

#pragma unroll
        for (int i = 0; i < 8; i++) {
            float4 f0 = *(const float4*)&fl[(row0 + i) * 128 + col0];
            float4 f1 = *(const float4*)&fl[(row0 + i) * 128 + col0 + 4];
            float fr[8] = {f0.x, f0.y, f0.z, f0.w, f1.x, f1.y, f1.z, f1.w};
            float s = 0.0f, sq = 0.0f;
#pragma unroll
            for (int j = 0; j < 8; j++) {
                float vv = acc[i][j] + bj[j] + fr[j];
                acc[i][j] = vv;
                s += vv;
                sq += vv * vv;
            }
#pragma unroll
            for (int off = 8; off; off >>= 1) {
                s  += __shfl_xor_sync(0xffffffffu, s, off);
                sq += __shfl_xor_sync(0xffffffffu, sq, off);
            }
            float mu = s * 0.0078125f;                       // /128
            float var = sq * 0.0078125f - mu * mu;
            float rstd = rsqrtf(var + 1e-5f);
            float4 o0, o1;
            o0.x = (acc[i][0] - mu) * rstd * gj[0] + ej[0];
            o0.y = (acc[i][1] - mu) * rstd * gj[1] + ej[1];
            o0.z = (acc[i][2] - mu) * rstd * gj[2] + ej[2];
            o0.w = (acc[i][3] - mu) * rstd * gj[3] + ej[3];
            o1.x = (acc[i][4] - mu) * rstd * gj[4] + ej[4];
            o1.y = (acc[i][5] - mu) * rstd * gj[5] + ej[5];
            o1.z = (acc[i][6] - mu) * rstd * gj[6] + ej[6];
            o1.w = (acc[i][7] - mu) * rstd * gj[7] + ej[7];
            *(float4*)&outp[(row0 + i) * 128 + col0]     = o0;
            *(float4*)&outp[(row0 + i) * 128 + col0 + 4] = o1;
        }
    }
}

// ---------------------------------------------------------------------------
extern "C" void kernel_launch(void* const* d_in, const int* in_sizes, int n_in,
                              void* d_out, int out_size) {
    const float* feat  = (const float*)d_in[0];
    const float* w     = (const float*)d_in[1];
    const float* W1    = (const float*)d_in[2];
    const float* b1    = (const float*)d_in[3];
    const float* W2    = (const float*)d_in[4];
    const float* b2    = (const float*)d_in[5];
    const float* gamma = (const float*)d_in[6];
    const float* beta  = (const float*)d_in[7];
    float* out = (float*)d_out;

    cudaFuncSetAttribute(fused_kernel, cudaFuncAttributeMaxDynamicSharedMemorySize,
                         SMEM_BYTES);

    wf_kernel<<<(Bn * Tt * Nn) / 8, 256>>>(feat, w);
    psum_kernel<<<Bn * Tt, 128>>>();
    fused_kernel<<<Bn * TWw, 256, SMEM_BYTES>>>(feat, W1, b1, W2, b2, gamma, beta, out);
}